// round 5
// baseline (speedup 1.0000x reference)
#include <cuda_runtime.h>
#include <cuda_bf16.h>
#include <cstdint>

// ---------------- problem dims ----------------
#define TT 2048
#define BB 16
#define DDIM 1024
#define MM (TT*BB)            // 32768 rows
#define SBD (BB*DDIM)         // 16384 lanes in scan
#define NELEM ((size_t)MM*DDIM)

// ---------------- device scratch (no cudaMalloc allowed) ----------------
__device__ int8_t g_x1[NELEM];
__device__ int8_t g_x0[NELEM];
__device__ int8_t g_w1[2*DDIM*DDIM];
__device__ int8_t g_w0[2*DDIM*DDIM];
__device__ float g_alpha[NELEM];
__device__ float g_vraw[NELEM];

// ---------------- PTX helpers (base sm_103 target: no tcgen05/TMA) ---------
__device__ __forceinline__ uint32_t smem_u32(const void* p) {
    uint32_t a;
    asm("{ .reg .u64 t; cvta.to.shared.u64 t, %1; cvt.u32.u64 %0, t; }" : "=r"(a) : "l"(p));
    return a;
}
__device__ __forceinline__ void cp16(uint32_t s, const void* g) {
    asm volatile("cp.async.cg.shared.global [%0], [%1], 16;" :: "r"(s), "l"(g));
}
__device__ __forceinline__ void cp_commit() {
    asm volatile("cp.async.commit_group;" ::: "memory");
}
template <int N>
__device__ __forceinline__ void cp_wait() {
    asm volatile("cp.async.wait_group %0;" :: "n"(N) : "memory");
}
__device__ __forceinline__ void ldsm4(uint32_t* r, uint32_t addr) {
    asm volatile("ldmatrix.sync.aligned.m8n8.x4.shared.b16 {%0,%1,%2,%3}, [%4];"
                 : "=r"(r[0]), "=r"(r[1]), "=r"(r[2]), "=r"(r[3]) : "r"(addr));
}
// s8 x s8 -> s32, m16n8k32
__device__ __forceinline__ void imma(int* c, const uint32_t* a, uint32_t b0, uint32_t b1) {
    asm volatile("mma.sync.aligned.m16n8k32.row.col.s32.s8.s8.s32 "
                 "{%0,%1,%2,%3}, {%4,%5,%6,%7}, {%8,%9}, {%0,%1,%2,%3};"
                 : "+r"(c[0]), "+r"(c[1]), "+r"(c[2]), "+r"(c[3])
                 : "r"(a[0]), "r"(a[1]), "r"(a[2]), "r"(a[3]), "r"(b0), "r"(b1));
}

// ---------------- quantization kernels (fp32 -> int8 hi/lo planes) ----------
// x = X1/16 + X0/2048 ; w = W1/2048 + W0/2^18 (power-of-2 scales, exact recon)
__global__ void quant_x_kernel(const float* __restrict__ x) {
    size_t i = (size_t)blockIdx.x * blockDim.x + threadIdx.x;  // float4 index
    if (i >= NELEM / 4) return;
    float4 v = reinterpret_cast<const float4*>(x)[i];
    float f[4] = {v.x, v.y, v.z, v.w};
    char h[4], lo[4];
#pragma unroll
    for (int j = 0; j < 4; j++) {
        float q1 = rintf(f[j] * 16.0f);
        q1 = fminf(fmaxf(q1, -127.0f), 127.0f);
        float rem = f[j] - q1 * 0.0625f;
        float q0 = rintf(rem * 2048.0f);
        q0 = fminf(fmaxf(q0, -127.0f), 127.0f);
        h[j]  = (char)(int)q1;
        lo[j] = (char)(int)q0;
    }
    reinterpret_cast<uint32_t*>(g_x1)[i] = *reinterpret_cast<uint32_t*>(h);
    reinterpret_cast<uint32_t*>(g_x0)[i] = *reinterpret_cast<uint32_t*>(lo);
}

__global__ void quant_w_kernel(const float* __restrict__ Wa, const float* __restrict__ Wx) {
    size_t i = (size_t)blockIdx.x * blockDim.x + threadIdx.x;  // float4 index over 2 mats
    const size_t nper = (size_t)DDIM * DDIM / 4;
    if (i >= 2 * nper) return;
    const float* src = (i < nper) ? Wa : Wx;
    size_t j = (i < nper) ? i : i - nper;
    float4 v = reinterpret_cast<const float4*>(src)[j];
    float f[4] = {v.x, v.y, v.z, v.w};
    char h[4], lo[4];
#pragma unroll
    for (int k = 0; k < 4; k++) {
        float q1 = rintf(f[k] * 2048.0f);
        q1 = fminf(fmaxf(q1, -127.0f), 127.0f);
        float rem = f[k] - q1 * 4.8828125e-4f;      // /2048
        float q0 = rintf(rem * 262144.0f);          // *2^18
        q0 = fminf(fmaxf(q0, -127.0f), 127.0f);
        h[k]  = (char)(int)q1;
        lo[k] = (char)(int)q0;
    }
    reinterpret_cast<uint32_t*>(g_w1)[i] = *reinterpret_cast<uint32_t*>(h);
    reinterpret_cast<uint32_t*>(g_w0)[i] = *reinterpret_cast<uint32_t*>(lo);
}

// ---------------- GEMM: out[m,e] = act( sum_d x[m,d]*W[e,d] + bias[e] ) ------
// int8 split via mma m16n8k32: ACC1 += X1*W1 ; ACC2 += X1*W0 + X0*W1
// z = ACC1*2^-15 + ACC2*2^-22 + bias. CTA 128x128x32, 256 thr, warp 64x32,
// 4-stage cp.async ring.
static constexpr int BK   = 32;              // int8 k-chunk bytes
static constexpr int ROWB = 48;              // 32B data + 16B pad
static constexpr int TILE_B = 128 * ROWB;    // 6144 per tensor
static constexpr int ST_X1 = 0;
static constexpr int ST_X0 = ST_X1 + TILE_B;
static constexpr int ST_W1 = ST_X0 + TILE_B;
static constexpr int ST_W0 = ST_W1 + TILE_B;
static constexpr int STAGE_B = ST_W0 + TILE_B;   // 24576
static constexpr int NSTAGE  = 4;
static constexpr int SMEM_GEMM_TOTAL = NSTAGE * STAGE_B;  // 98304
static constexpr int NKC = DDIM / BK;        // 32

__global__ void __launch_bounds__(256, 1)
gemm_kernel(const float* __restrict__ bias, int ws) {
    extern __shared__ char smem[];
    const uint32_t sbase = smem_u32(smem);
    const int tid = threadIdx.x;
    const int wid = tid >> 5;
    const int l   = tid & 31;
    const int wid_m = wid >> 2;      // 0..1  (64-row slabs)
    const int wid_n = wid & 3;       // 0..3  (32-col slabs)
    const int bn = blockIdx.x;       // 0..7   (N tiles of 128)
    const int bm = blockIdx.y;       // 0..255 (M tiles of 128)

    const int8_t* __restrict__ X1g = g_x1 + (size_t)bm * 128 * DDIM;
    const int8_t* __restrict__ X0g = g_x0 + (size_t)bm * 128 * DDIM;
    const int8_t* __restrict__ W1g = g_w1 + (size_t)ws * DDIM * DDIM + (size_t)bn * 128 * DDIM;
    const int8_t* __restrict__ W0g = g_w0 + (size_t)ws * DDIM * DDIM + (size_t)bn * 128 * DDIM;
    float* __restrict__ outp = ws ? g_vraw : g_alpha;

    // cp.async mapping: 256 threads; each tensor tile = 128 rows x 2 chunks of 16B.
    const int crow = tid & 127;      // row 0..127
    const int chalf = tid >> 7;      // 0/1: which 16B half of the 32B k-slice
    auto issue_stage = [&](int stage, int kc) {
        const uint32_t s0 = sbase + stage * STAGE_B;
        const size_t goff = (size_t)crow * DDIM + (size_t)kc * BK + chalf * 16;
        const uint32_t so = crow * ROWB + chalf * 16;
        cp16(s0 + ST_X1 + so, X1g + goff);
        cp16(s0 + ST_X0 + so, X0g + goff);
        cp16(s0 + ST_W1 + so, W1g + goff);
        cp16(s0 + ST_W0 + so, W0g + goff);
        cp_commit();
    };

    // ldmatrix lane offset: lanes 0-7 rows0-7 +0 | 8-15 rows8-15 +0 |
    //                       16-23 rows0-7 +16 | 24-31 rows8-15 +16
    const uint32_t lane_off = (uint32_t)((l & 15) * ROWB + (l >> 4) * 16);

    int acc1[4][4][4], acc2[4][4][4];
#pragma unroll
    for (int mi = 0; mi < 4; mi++)
#pragma unroll
        for (int ni = 0; ni < 4; ni++)
#pragma unroll
            for (int r = 0; r < 4; r++) { acc1[mi][ni][r] = 0; acc2[mi][ni][r] = 0; }

    issue_stage(0, 0);
    issue_stage(1, 1);
    issue_stage(2, 2);

    int rd = 0, wr = 3;
#pragma unroll 1
    for (int kc = 0; kc < NKC; kc++) {
        if (kc <= NKC - 3)      cp_wait<2>();
        else if (kc == NKC - 2) cp_wait<1>();
        else                    cp_wait<0>();
        __syncthreads();
        if (kc + 3 < NKC) issue_stage(wr, kc + 3);

        const uint32_t s0 = sbase + rd * STAGE_B;
        const uint32_t sX1 = s0 + ST_X1 + (uint32_t)(wid_m * 64 * ROWB) + lane_off;
        const uint32_t sX0 = s0 + ST_X0 + (uint32_t)(wid_m * 64 * ROWB) + lane_off;
        const uint32_t sW1 = s0 + ST_W1 + (uint32_t)(wid_n * 32 * ROWB) + lane_off;
        const uint32_t sW0 = s0 + ST_W0 + (uint32_t)(wid_n * 32 * ROWB) + lane_off;

        // B fragments: pair p covers n-rows p*16..p*16+15; regs {r0,r2}=even n8, {r1,r3}=odd
        uint32_t w1r[2][4], w0r[2][4];
#pragma unroll
        for (int p = 0; p < 2; p++) {
            ldsm4(w1r[p], sW1 + p * 16 * ROWB);
            ldsm4(w0r[p], sW0 + p * 16 * ROWB);
        }
#pragma unroll
        for (int mi = 0; mi < 4; mi++) {
            uint32_t x1[4], x0[4];
            ldsm4(x1, sX1 + mi * 16 * ROWB);
            ldsm4(x0, sX0 + mi * 16 * ROWB);
#pragma unroll
            for (int n8 = 0; n8 < 4; n8++) {
                const int p = n8 >> 1, q = n8 & 1;
                const uint32_t b1lo = w1r[p][q], b1hi = w1r[p][q + 2];
                const uint32_t b0lo = w0r[p][q], b0hi = w0r[p][q + 2];
                imma(acc1[mi][n8], x1, b1lo, b1hi);
                imma(acc2[mi][n8], x1, b0lo, b0hi);
                imma(acc2[mi][n8], x0, b1lo, b1hi);
            }
        }
        rd = (rd + 1) & 3;
        wr = (wr + 1) & 3;
    }

    // epilogue: z = acc1*2^-15 + acc2*2^-22 + bias; activation; float2 stores
    const float S1 = 3.0517578125e-05f;      // 2^-15
    const float S2 = 2.384185791015625e-07f; // 2^-22
    const int row_base = bm * 128 + wid_m * 64 + (l >> 2);
    const int col_base = bn * 128 + wid_n * 32 + (l & 3) * 2;
#pragma unroll
    for (int mi = 0; mi < 4; mi++) {
#pragma unroll
        for (int n8 = 0; n8 < 4; n8++) {
            const int col = col_base + n8 * 8;
            const float bia0 = __ldg(&bias[col]);
            const float bia1 = __ldg(&bias[col + 1]);
#pragma unroll
            for (int half = 0; half < 2; half++) {
                const int row = row_base + mi * 16 + half * 8;
                float v0 = fmaf((float)acc1[mi][n8][half*2+0], S1,
                           fmaf((float)acc2[mi][n8][half*2+0], S2, bia0));
                float v1 = fmaf((float)acc1[mi][n8][half*2+1], S1,
                           fmaf((float)acc2[mi][n8][half*2+1], S2, bia1));
                float2 o;
                if (ws) { o.x = tanhf(v0); o.y = tanhf(v1); }
                else {
                    o.x = __fdividef(1.0f, 1.0f + __expf(-v0));
                    o.y = __fdividef(1.0f, 1.0f + __expf(-v1));
                }
                *reinterpret_cast<float2*>(outp + (size_t)row * DDIM + col) = o;
            }
        }
    }
}

// ---------------- scan kernel: 16384 independent recurrences over T ----------
__global__ void __launch_bounds__(32)
scan_kernel(const float* __restrict__ d_g, const float* __restrict__ b_g,
            float* __restrict__ out) {
    const int idx = blockIdx.x * 32 + threadIdx.x;   // 0..16383
    const int d = idx & (DDIM - 1);
    const float LOG2E = 1.4426950408889634f;
    const float dgl = __ldg(&d_g[d]) * LOG2E;
    const float bgl = __ldg(&b_g[d]) * LOG2E;

    float* houtp = out + (size_t)TT * SBD;   // h buffer [T+1, B, D]
    houtp[idx] = 0.0f;                       // h0

    const float* A = g_alpha;
    const float* V = g_vraw;

    float paA[8], pvA[8], paB[8], pvB[8];
#pragma unroll
    for (int i = 0; i < 8; i++) {
        paA[i] = __ldg(&A[(size_t)i * SBD + idx]);
        pvA[i] = __ldg(&V[(size_t)i * SBD + idx]);
        paB[i] = __ldg(&A[(size_t)(i + 8) * SBD + idx]);
        pvB[i] = __ldg(&V[(size_t)(i + 8) * SBD + idx]);
    }

    float h = 0.0f;

#define SCAN8(CA, CV, TBASE)                                                    \
    do {                                                                        \
        _Pragma("unroll")                                                       \
        for (int i = 0; i < 8; i++) {                                           \
            const float a = CA[i];                                              \
            const float c = (1.0f - a) * CV[i];                                 \
            const float ah = a * h;                                             \
            const float ex = exp2f(fmaf(dgl, fabsf(h), -bgl));                  \
            const float g = __fdividef(1.0f, 1.0f + ex);                        \
            h = fmaf(c, g, ah);                                                 \
            const float sg = __fdividef(1.0f, 1.0f + exp2f(-h * LOG2E));        \
            const size_t t = (size_t)((TBASE) + i);                             \
            out[t * SBD + idx] = h * h * sg;                                    \
            houtp[(t + 1) * SBD + idx] = h;                                     \
        }                                                                       \
    } while (0)

#pragma unroll 1
    for (int t0 = 0; t0 < TT; t0 += 16) {
        float ca[8], cv[8];
#pragma unroll
        for (int i = 0; i < 8; i++) { ca[i] = paA[i]; cv[i] = pvA[i]; }
        if (t0 + 16 < TT) {
#pragma unroll
            for (int i = 0; i < 8; i++) {
                paA[i] = __ldg(&A[(size_t)(t0 + 16 + i) * SBD + idx]);
                pvA[i] = __ldg(&V[(size_t)(t0 + 16 + i) * SBD + idx]);
            }
        }
        SCAN8(ca, cv, t0);

#pragma unroll
        for (int i = 0; i < 8; i++) { ca[i] = paB[i]; cv[i] = pvB[i]; }
        if (t0 + 24 < TT) {
#pragma unroll
            for (int i = 0; i < 8; i++) {
                paB[i] = __ldg(&A[(size_t)(t0 + 24 + i) * SBD + idx]);
                pvB[i] = __ldg(&V[(size_t)(t0 + 24 + i) * SBD + idx]);
            }
        }
        SCAN8(ca, cv, t0 + 8);
    }
#undef SCAN8
}

// ---------------- launcher ----------------
extern "C" void kernel_launch(void* const* d_in, const int* in_sizes, int n_in,
                              void* d_out, int out_size) {
    const float* x       = (const float*)d_in[0];
    const float* W_alpha = (const float*)d_in[1];
    const float* b_alpha = (const float*)d_in[2];
    const float* d_g     = (const float*)d_in[3];
    const float* b_g     = (const float*)d_in[4];
    const float* W_x     = (const float*)d_in[5];
    const float* b_v     = (const float*)d_in[6];
    float* out = (float*)d_out;

    (void)in_sizes; (void)n_in; (void)out_size;

    cudaFuncSetAttribute(gemm_kernel, cudaFuncAttributeMaxDynamicSharedMemorySize,
                         SMEM_GEMM_TOTAL);

    // 1) quantize fp32 -> int8 hi/lo planes
    {
        const int n4 = (int)(NELEM / 4);
        quant_x_kernel<<<(n4 + 255) / 256, 256>>>(x);
        const int w4 = 2 * DDIM * DDIM / 4;
        quant_w_kernel<<<(w4 + 255) / 256, 256>>>(W_alpha, W_x);
    }

    // 2) two fused GEMM + activation launches (alpha: sigmoid; vraw: tanh)
    {
        dim3 grid(DDIM / 128, MM / 128);
        gemm_kernel<<<grid, 256, SMEM_GEMM_TOTAL>>>(b_alpha, 0);
        gemm_kernel<<<grid, 256, SMEM_GEMM_TOTAL>>>(b_v, 1);
    }

    // 3) sequential scan, fully parallel over B*D lanes
    scan_kernel<<<SBD / 32, 32>>>(d_g, b_g, out);
}

// round 7
// speedup vs baseline: 2.8794x; 2.8794x over previous
#include <cuda_runtime.h>
#include <cuda_fp16.h>
#include <cstdint>

// ---------------- problem dims ----------------
#define TT 2048
#define BB 16
#define DDIM 1024
#define MM (TT*BB)            // 32768 rows
#define SBD (BB*DDIM)         // 16384 lanes in scan
#define NELEM ((size_t)MM*DDIM)

// ---------------- device scratch (no cudaMalloc allowed) ----------------
__device__ __half g_xh[NELEM];
__device__ __half g_wh[2*DDIM*DDIM];
__device__ __half g_wl[2*DDIM*DDIM];   // (w - wh) * 2048
__device__ float g_alpha[NELEM];
__device__ float g_vraw[NELEM];

// ---------------- PTX helpers (base sm_103 target: no tcgen05/TMA) ---------
__device__ __forceinline__ uint32_t smem_u32(const void* p) {
    uint32_t a;
    asm("{ .reg .u64 t; cvta.to.shared.u64 t, %1; cvt.u32.u64 %0, t; }" : "=r"(a) : "l"(p));
    return a;
}
__device__ __forceinline__ void cp16(uint32_t s, const void* g) {
    asm volatile("cp.async.cg.shared.global [%0], [%1], 16;" :: "r"(s), "l"(g));
}
__device__ __forceinline__ void cp_commit() {
    asm volatile("cp.async.commit_group;" ::: "memory");
}
template <int N>
__device__ __forceinline__ void cp_wait() {
    asm volatile("cp.async.wait_group %0;" :: "n"(N) : "memory");
}
__device__ __forceinline__ void ldsm4(uint32_t* r, uint32_t addr) {
    asm volatile("ldmatrix.sync.aligned.m8n8.x4.shared.b16 {%0,%1,%2,%3}, [%4];"
                 : "=r"(r[0]), "=r"(r[1]), "=r"(r[2]), "=r"(r[3]) : "r"(addr));
}
__device__ __forceinline__ void hmma(float* c, const uint32_t* a, uint32_t b0, uint32_t b1) {
    asm volatile("mma.sync.aligned.m16n8k16.row.col.f32.f16.f16.f32 "
                 "{%0,%1,%2,%3}, {%4,%5,%6,%7}, {%8,%9}, {%0,%1,%2,%3};"
                 : "+f"(c[0]), "+f"(c[1]), "+f"(c[2]), "+f"(c[3])
                 : "r"(a[0]), "r"(a[1]), "r"(a[2]), "r"(a[3]), "r"(b0), "r"(b1));
}

// ---------------- quantization kernels ----------------
__global__ void quant_x_kernel(const float* __restrict__ x) {
    size_t i = (size_t)blockIdx.x * blockDim.x + threadIdx.x;  // float4 index
    if (i >= NELEM / 4) return;
    float4 v = reinterpret_cast<const float4*>(x)[i];
    float f[4] = {v.x, v.y, v.z, v.w};
    union { __half h[4]; uint2 u; } H;
#pragma unroll
    for (int j = 0; j < 4; j++) H.h[j] = __float2half_rn(f[j]);
    reinterpret_cast<uint2*>(g_xh)[i] = H.u;
}

__global__ void quant_w_kernel(const float* __restrict__ Wa, const float* __restrict__ Wx) {
    size_t i = (size_t)blockIdx.x * blockDim.x + threadIdx.x;  // float4 idx over 2 mats
    const size_t nper = (size_t)DDIM * DDIM / 4;
    if (i >= 2 * nper) return;
    const float* src = (i < nper) ? Wa : Wx;
    size_t j = (i < nper) ? i : i - nper;
    float4 v = reinterpret_cast<const float4*>(src)[j];
    float f[4] = {v.x, v.y, v.z, v.w};
    union { __half h[4]; uint2 u; } H, L;
#pragma unroll
    for (int k = 0; k < 4; k++) {
        __half hh = __float2half_rn(f[k]);
        H.h[k] = hh;
        L.h[k] = __float2half_rn((f[k] - __half2float(hh)) * 2048.0f);
    }
    reinterpret_cast<uint2*>(g_wh)[i] = H.u;
    reinterpret_cast<uint2*>(g_wl)[i] = L.u;
}

// ---------------- GEMM: out[m,e] = act( sum_d x[m,d]*W[e,d] + bias[e] ) ------
// fp16 2-term: z = xh*wh + (xh*wl)*2^-11 + bias. CTA 128x128x32, 256 thr
// (8 warps, warp tile 64x32), 4-stage cp.async ring.
static constexpr int BK   = 32;              // k elems per chunk (64B of fp16)
static constexpr int ROWB = 80;              // 64B data + 16B pad
static constexpr int TILE_B = 128 * ROWB;    // 10240 per tensor
static constexpr int ST_XH = 0;
static constexpr int ST_WH = ST_XH + TILE_B;
static constexpr int ST_WL = ST_WH + TILE_B;
static constexpr int STAGE_B = ST_WL + TILE_B;   // 30720
static constexpr int NSTAGE  = 4;
static constexpr int SMEM_GEMM_TOTAL = NSTAGE * STAGE_B;  // 122880
static constexpr int NKC = DDIM / BK;        // 32

__global__ void __launch_bounds__(256, 1)
gemm_kernel(const float* __restrict__ bias, int ws) {
    extern __shared__ char smem[];
    const uint32_t sbase = smem_u32(smem);
    const int tid = threadIdx.x;
    const int wid = tid >> 5;
    const int l   = tid & 31;
    const int wid_m = wid >> 2;      // 0..1  (64-row slabs)
    const int wid_n = wid & 3;       // 0..3  (32-col slabs)
    const int bn = blockIdx.x;       // 0..7   (N tiles of 128)
    const int bm = blockIdx.y;       // 0..255 (M tiles of 128)

    const __half* __restrict__ Xg  = g_xh + (size_t)bm * 128 * DDIM;
    const __half* __restrict__ Whg = g_wh + (size_t)ws * DDIM * DDIM + (size_t)bn * 128 * DDIM;
    const __half* __restrict__ Wlg = g_wl + (size_t)ws * DDIM * DDIM + (size_t)bn * 128 * DDIM;
    float* __restrict__ outp = ws ? g_vraw : g_alpha;

    // cp.async mapping: 256 threads; each tile 128 rows x 64B; 2 thr/row, 2x16B each
    const int crow = tid >> 1;
    const int chlf = tid & 1;
    auto issue_stage = [&](int stage, int kc) {
        const uint32_t s0 = sbase + stage * STAGE_B;
        const size_t gof = (size_t)crow * DDIM + (size_t)kc * BK + chlf * 16;  // halves
        const uint32_t so = crow * ROWB + chlf * 32;
        cp16(s0 + ST_XH + so,      Xg  + gof);
        cp16(s0 + ST_XH + so + 16, Xg  + gof + 8);
        cp16(s0 + ST_WH + so,      Whg + gof);
        cp16(s0 + ST_WH + so + 16, Whg + gof + 8);
        cp16(s0 + ST_WL + so,      Wlg + gof);
        cp16(s0 + ST_WL + so + 16, Wlg + gof + 8);
        cp_commit();
    };

    // ldmatrix lane offsets (validated in R3, ROWB=80 mod-128 conflict-free)
    // B map: lanes 0-7 -> n0-7/k0-7 | 8-15 -> n0-7/k8-15 | 16-23 -> n8-15/k0-7
    //        | 24-31 -> n8-15/k8-15  =>  B regs for n-slice q are {r[2q], r[2q+1]}
    const uint32_t a_lane_off = (uint32_t)((l & 15) * ROWB + (l >> 4) * 16);
    const uint32_t b_lane_off = (uint32_t)(((l & 7) + ((l >> 4) << 3)) * ROWB + ((l >> 3) & 1) * 16);

    float acc1[4][4][4], acc2[4][4][4];
#pragma unroll
    for (int mi = 0; mi < 4; mi++)
#pragma unroll
        for (int ni = 0; ni < 4; ni++)
#pragma unroll
            for (int r = 0; r < 4; r++) { acc1[mi][ni][r] = 0.0f; acc2[mi][ni][r] = 0.0f; }

    issue_stage(0, 0);
    issue_stage(1, 1);
    issue_stage(2, 2);

    int rd = 0, wr = 3;
#pragma unroll 1
    for (int kc = 0; kc < NKC; kc++) {
        if (kc <= NKC - 3)      cp_wait<2>();
        else if (kc == NKC - 2) cp_wait<1>();
        else                    cp_wait<0>();
        __syncthreads();
        if (kc + 3 < NKC) issue_stage(wr, kc + 3);

        const uint32_t s0 = sbase + rd * STAGE_B;
        const uint32_t sXH = s0 + ST_XH + (uint32_t)(wid_m * 64 * ROWB) + a_lane_off;
        const uint32_t sWH = s0 + ST_WH + (uint32_t)(wid_n * 32 * ROWB) + b_lane_off;
        const uint32_t sWL = s0 + ST_WL + (uint32_t)(wid_n * 32 * ROWB) + b_lane_off;

#pragma unroll
        for (int ks = 0; ks < 2; ks++) {
            uint32_t bh[2][4], bl[2][4];
#pragma unroll
            for (int p = 0; p < 2; p++) {
                ldsm4(bh[p], sWH + p * 16 * ROWB + ks * 32);
                ldsm4(bl[p], sWL + p * 16 * ROWB + ks * 32);
            }
#pragma unroll
            for (int mi = 0; mi < 4; mi++) {
                uint32_t ah[4];
                ldsm4(ah, sXH + mi * 16 * ROWB + ks * 32);
#pragma unroll
                for (int n8 = 0; n8 < 4; n8++) {
                    const int p = n8 >> 1, q = n8 & 1;
                    hmma(acc1[mi][n8], ah, bh[p][q * 2], bh[p][q * 2 + 1]);
                    hmma(acc2[mi][n8], ah, bl[p][q * 2], bl[p][q * 2 + 1]);
                }
            }
        }
        rd = (rd + 1) & 3;
        wr = (wr + 1) & 3;
    }

    // epilogue: z = acc1 + acc2*2^-11 + bias; activation; float2 stores
    const float S2 = 4.8828125e-4f;   // 1/2048
    const int row_base = bm * 128 + wid_m * 64 + (l >> 2);
    const int col_base = bn * 128 + wid_n * 32 + (l & 3) * 2;
#pragma unroll
    for (int mi = 0; mi < 4; mi++) {
#pragma unroll
        for (int n8 = 0; n8 < 4; n8++) {
            const int col = col_base + n8 * 8;
            const float bia0 = __ldg(&bias[col]);
            const float bia1 = __ldg(&bias[col + 1]);
#pragma unroll
            for (int half = 0; half < 2; half++) {
                const int row = row_base + mi * 16 + half * 8;
                float v0 = fmaf(acc2[mi][n8][half*2+0], S2, acc1[mi][n8][half*2+0]) + bia0;
                float v1 = fmaf(acc2[mi][n8][half*2+1], S2, acc1[mi][n8][half*2+1]) + bia1;
                float2 o;
                if (ws) { o.x = tanhf(v0); o.y = tanhf(v1); }
                else {
                    o.x = __fdividef(1.0f, 1.0f + __expf(-v0));
                    o.y = __fdividef(1.0f, 1.0f + __expf(-v1));
                }
                *reinterpret_cast<float2*>(outp + (size_t)row * DDIM + col) = o;
            }
        }
    }
}

// ---------------- scan kernel: 16384 independent recurrences over T ----------
// 32-thread blocks; 4-slot cp.async smem ring, 8 steps/chunk, 2-chunk lead.
__global__ void __launch_bounds__(32)
scan_kernel(const float* __restrict__ d_g, const float* __restrict__ b_g,
            float* __restrict__ out) {
    __shared__ __align__(16) float sA[4][8][32];
    __shared__ __align__(16) float sV[4][8][32];
    const int lane = threadIdx.x;
    const int base = blockIdx.x * 32;
    const int idx = base + lane;
    const int d = idx & (DDIM - 1);
    const float LOG2E = 1.4426950408889634f;
    const float dgl = __ldg(&d_g[d]) * LOG2E;
    const float bgl = __ldg(&b_g[d]) * LOG2E;

    float* houtp = out + (size_t)TT * SBD;   // h buffer [T+1, B, D]
    houtp[idx] = 0.0f;                       // h0

    const float* A = g_alpha;
    const float* V = g_vraw;

    const int seg = lane & 7;        // 16B segment within a 128B row
    const int r0  = lane >> 3;       // 0..3

    auto issue_chunk = [&](int c) {
        const int slot = c & 3;
#pragma unroll
        for (int rr = 0; rr < 4; rr++) {
            const int r = r0 + rr * 4;             // 0..15
            const int step = r & 7;
            const size_t gidx = (size_t)(c * 8 + step) * SBD + base + seg * 4;
            const float* src = (r < 8) ? (A + gidx) : (V + gidx);
            float* dst = (r < 8) ? &sA[slot][step][seg * 4] : &sV[slot][step][seg * 4];
            cp16(smem_u32(dst), src);
        }
        cp_commit();
    };

    issue_chunk(0);
    issue_chunk(1);
    issue_chunk(2);

    float h = 0.0f;
#pragma unroll 1
    for (int t0 = 0; t0 < TT; t0 += 8) {
        __syncwarp();
        if (t0 + 24 < TT)       { issue_chunk((t0 >> 3) + 3); cp_wait<3>(); }
        else if (t0 + 24 == TT) cp_wait<2>();
        else if (t0 + 16 == TT) cp_wait<1>();
        else                    cp_wait<0>();
        __syncwarp();

        const int slot = (t0 >> 3) & 3;
#pragma unroll
        for (int i = 0; i < 8; i++) {
            const float a  = sA[slot][i][lane];
            const float cv = sV[slot][i][lane];
            const float c  = (1.0f - a) * cv;      // off critical chain
            const float ah = a * h;                // parallel with g-chain
            const float ex = exp2f(fmaf(dgl, fabsf(h), -bgl));
            const float g = __fdividef(1.0f, 1.0f + ex);
            h = fmaf(c, g, ah);                    // h_new
            const float sg = __fdividef(1.0f, 1.0f + exp2f(-h * LOG2E));
            const size_t t = (size_t)(t0 + i);
            out[t * SBD + idx] = h * h * sg;       // h * silu(h)
            houtp[(t + 1) * SBD + idx] = h;
        }
    }
}

// ---------------- launcher ----------------
extern "C" void kernel_launch(void* const* d_in, const int* in_sizes, int n_in,
                              void* d_out, int out_size) {
    const float* x       = (const float*)d_in[0];
    const float* W_alpha = (const float*)d_in[1];
    const float* b_alpha = (const float*)d_in[2];
    const float* d_g     = (const float*)d_in[3];
    const float* b_g     = (const float*)d_in[4];
    const float* W_x     = (const float*)d_in[5];
    const float* b_v     = (const float*)d_in[6];
    float* out = (float*)d_out;

    (void)in_sizes; (void)n_in; (void)out_size;

    cudaFuncSetAttribute(gemm_kernel, cudaFuncAttributeMaxDynamicSharedMemorySize,
                         SMEM_GEMM_TOTAL);

    // 1) quantize: x -> fp16; W -> fp16 hi + scaled lo
    {
        const int n4 = (int)(NELEM / 4);
        quant_x_kernel<<<(n4 + 255) / 256, 256>>>(x);
        const int w4 = 2 * DDIM * DDIM / 4;
        quant_w_kernel<<<(w4 + 255) / 256, 256>>>(W_alpha, W_x);
    }

    // 2) two fused GEMM + activation launches (alpha: sigmoid; vraw: tanh)
    {
        dim3 grid(DDIM / 128, MM / 128);
        gemm_kernel<<<grid, 256, SMEM_GEMM_TOTAL>>>(b_alpha, 0);
        gemm_kernel<<<grid, 256, SMEM_GEMM_TOTAL>>>(b_v, 1);
    }

    // 3) sequential scan, fully parallel over B*D lanes
    scan_kernel<<<SBD / 32, 32>>>(d_g, b_g, out);
}

// round 8
// speedup vs baseline: 3.4838x; 1.2099x over previous
#include <cuda_runtime.h>
#include <cuda_fp16.h>
#include <cstdint>

// ---------------- problem dims ----------------
#define TT 2048
#define BB 16
#define DDIM 1024
#define MM (TT*BB)            // 32768 rows
#define SBD (BB*DDIM)         // 16384 lanes in scan
#define NELEM ((size_t)MM*DDIM)

// ---------------- device scratch (no cudaMalloc allowed) ----------------
__device__ __half g_xh[NELEM];
__device__ __half g_wh[2*DDIM*DDIM];
__device__ __half g_wl[2*DDIM*DDIM];   // w - wh (raw residual, may be subnormal)
__device__ float g_alpha[NELEM];
__device__ float g_vraw[NELEM];

// ---------------- PTX helpers (base sm_103 target: no tcgen05/TMA) ---------
__device__ __forceinline__ uint32_t smem_u32(const void* p) {
    uint32_t a;
    asm("{ .reg .u64 t; cvta.to.shared.u64 t, %1; cvt.u32.u64 %0, t; }" : "=r"(a) : "l"(p));
    return a;
}
__device__ __forceinline__ void cp16(uint32_t s, const void* g) {
    asm volatile("cp.async.cg.shared.global [%0], [%1], 16;" :: "r"(s), "l"(g));
}
__device__ __forceinline__ void cp_commit() {
    asm volatile("cp.async.commit_group;" ::: "memory");
}
template <int N>
__device__ __forceinline__ void cp_wait() {
    asm volatile("cp.async.wait_group %0;" :: "n"(N) : "memory");
}
__device__ __forceinline__ void ldsm4(uint32_t* r, uint32_t addr) {
    asm volatile("ldmatrix.sync.aligned.m8n8.x4.shared.b16 {%0,%1,%2,%3}, [%4];"
                 : "=r"(r[0]), "=r"(r[1]), "=r"(r[2]), "=r"(r[3]) : "r"(addr));
}
__device__ __forceinline__ void hmma(float* c, const uint32_t* a, uint32_t b0, uint32_t b1) {
    asm volatile("mma.sync.aligned.m16n8k16.row.col.f32.f16.f16.f32 "
                 "{%0,%1,%2,%3}, {%4,%5,%6,%7}, {%8,%9}, {%0,%1,%2,%3};"
                 : "+f"(c[0]), "+f"(c[1]), "+f"(c[2]), "+f"(c[3])
                 : "r"(a[0]), "r"(a[1]), "r"(a[2]), "r"(a[3]), "r"(b0), "r"(b1));
}

// ---------------- quantization kernels ----------------
__global__ void quant_x_kernel(const float* __restrict__ x) {
    size_t i = (size_t)blockIdx.x * blockDim.x + threadIdx.x;  // float4 index
    if (i >= NELEM / 4) return;
    float4 v = reinterpret_cast<const float4*>(x)[i];
    float f[4] = {v.x, v.y, v.z, v.w};
    union { __half h[4]; uint2 u; } H;
#pragma unroll
    for (int j = 0; j < 4; j++) H.h[j] = __float2half_rn(f[j]);
    reinterpret_cast<uint2*>(g_xh)[i] = H.u;
}

__global__ void quant_w_kernel(const float* __restrict__ Wa, const float* __restrict__ Wx) {
    size_t i = (size_t)blockIdx.x * blockDim.x + threadIdx.x;  // float4 idx over 2 mats
    const size_t nper = (size_t)DDIM * DDIM / 4;
    if (i >= 2 * nper) return;
    const float* src = (i < nper) ? Wa : Wx;
    size_t j = (i < nper) ? i : i - nper;
    float4 v = reinterpret_cast<const float4*>(src)[j];
    float f[4] = {v.x, v.y, v.z, v.w};
    union { __half h[4]; uint2 u; } H, L;
#pragma unroll
    for (int k = 0; k < 4; k++) {
        __half hh = __float2half_rn(f[k]);
        H.h[k] = hh;
        L.h[k] = __float2half_rn(f[k] - __half2float(hh));   // raw residual
    }
    reinterpret_cast<uint2*>(g_wh)[i] = H.u;
    reinterpret_cast<uint2*>(g_wl)[i] = L.u;
}

// ---------------- GEMM: out[m,e] = act( sum_d x[m,d]*W[e,d] + bias[e] ) ------
// fp16 2-term, SINGLE fp32 accumulator: z = sum xh*(wh [+] wl) + bias.
// CTA 128x256x32, 512 thr (16 warps, warp tile 32x64), 4-stage cp.async ring.
static constexpr int BK   = 32;              // k elems per chunk (64B of fp16)
static constexpr int ROWB = 80;              // 64B data + 16B pad
static constexpr int XH_TILE_B = 128 * ROWB; // 10240
static constexpr int W_TILE_B  = 256 * ROWB; // 20480
static constexpr int ST_XH = 0;
static constexpr int ST_WH = ST_XH + XH_TILE_B;
static constexpr int ST_WL = ST_WH + W_TILE_B;
static constexpr int STAGE_B = ST_WL + W_TILE_B;   // 51200
static constexpr int NSTAGE  = 4;
static constexpr int SMEM_GEMM_TOTAL = NSTAGE * STAGE_B;  // 204800
static constexpr int NKC = DDIM / BK;        // 32

__global__ void __launch_bounds__(512, 1)
gemm_kernel(const float* __restrict__ bias, int ws) {
    extern __shared__ char smem[];
    const uint32_t sbase = smem_u32(smem);
    const int tid = threadIdx.x;
    const int wid = tid >> 5;
    const int l   = tid & 31;
    const int wid_m = wid >> 2;      // 0..3  (32-row slabs)
    const int wid_n = wid & 3;       // 0..3  (64-col slabs)
    const int bn = blockIdx.x;       // 0..3   (N tiles of 256)
    const int bm = blockIdx.y;       // 0..255 (M tiles of 128)

    const __half* __restrict__ Xg  = g_xh + (size_t)bm * 128 * DDIM;
    const __half* __restrict__ Whg = g_wh + (size_t)ws * DDIM * DDIM + (size_t)bn * 256 * DDIM;
    const __half* __restrict__ Wlg = g_wl + (size_t)ws * DDIM * DDIM + (size_t)bn * 256 * DDIM;
    float* __restrict__ outp = ws ? g_vraw : g_alpha;

    // cp.async mapping: 512 threads. XH: 128 rows x 4 segs = 512 (1/thr);
    // WH/WL: 256 rows x 4 segs = 1024 (2/thr each). 5 cp16/thread.
    const int crow = tid >> 2;       // 0..127
    const int cseg = tid & 3;        // 16B segment
    auto issue_stage = [&](int stage, int kc) {
        const uint32_t s0 = sbase + stage * STAGE_B;
        const size_t gof = (size_t)kc * BK + cseg * 8;    // in halves
        const uint32_t so = cseg * 16;
        cp16(s0 + ST_XH + crow * ROWB + so, Xg + (size_t)crow * DDIM + gof);
#pragma unroll
        for (int r2 = 0; r2 < 2; r2++) {
            const int r = crow + r2 * 128;
            cp16(s0 + ST_WH + r * ROWB + so, Whg + (size_t)r * DDIM + gof);
            cp16(s0 + ST_WL + r * ROWB + so, Wlg + (size_t)r * DDIM + gof);
        }
        cp_commit();
    };

    // ldmatrix lane offsets (ROWB=80 mod-128 conflict-free, validated R3/R7)
    // B map: n-slice q within an x4 load uses regs {r[2q], r[2q+1]}
    const uint32_t a_lane_off = (uint32_t)((l & 15) * ROWB + (l >> 4) * 16);
    const uint32_t b_lane_off = (uint32_t)(((l & 7) + ((l >> 4) << 3)) * ROWB + ((l >> 3) & 1) * 16);

    float acc[2][8][4];
#pragma unroll
    for (int mi = 0; mi < 2; mi++)
#pragma unroll
        for (int ni = 0; ni < 8; ni++)
#pragma unroll
            for (int r = 0; r < 4; r++) acc[mi][ni][r] = 0.0f;

    issue_stage(0, 0);
    issue_stage(1, 1);
    issue_stage(2, 2);

    int rd = 0, wr = 3;
#pragma unroll 1
    for (int kc = 0; kc < NKC; kc++) {
        if (kc <= NKC - 3)      cp_wait<2>();
        else if (kc == NKC - 2) cp_wait<1>();
        else                    cp_wait<0>();
        __syncthreads();
        if (kc + 3 < NKC) issue_stage(wr, kc + 3);

        const uint32_t s0 = sbase + rd * STAGE_B;
        const uint32_t sXH = s0 + ST_XH + (uint32_t)(wid_m * 32 * ROWB) + a_lane_off;
        const uint32_t sWH = s0 + ST_WH + (uint32_t)(wid_n * 64 * ROWB) + b_lane_off;
        const uint32_t sWL = s0 + ST_WL + (uint32_t)(wid_n * 64 * ROWB) + b_lane_off;

#pragma unroll
        for (int ks = 0; ks < 2; ks++) {
            uint32_t ah[2][4];
            ldsm4(ah[0], sXH + ks * 32);
            ldsm4(ah[1], sXH + 16 * ROWB + ks * 32);
#pragma unroll
            for (int p = 0; p < 4; p++) {
                uint32_t bh[4], bl[4];
                ldsm4(bh, sWH + p * 16 * ROWB + ks * 32);
                ldsm4(bl, sWL + p * 16 * ROWB + ks * 32);
#pragma unroll
                for (int mi = 0; mi < 2; mi++) {
                    hmma(acc[mi][2*p+0], ah[mi], bh[0], bh[1]);
                    hmma(acc[mi][2*p+1], ah[mi], bh[2], bh[3]);
                    hmma(acc[mi][2*p+0], ah[mi], bl[0], bl[1]);
                    hmma(acc[mi][2*p+1], ah[mi], bl[2], bl[3]);
                }
            }
        }
        rd = (rd + 1) & 3;
        wr = (wr + 1) & 3;
    }

    // epilogue: z = acc + bias; activation; float2 stores
    const int row_base = bm * 128 + wid_m * 32 + (l >> 2);
    const int col_base = bn * 256 + wid_n * 64 + (l & 3) * 2;
#pragma unroll
    for (int mi = 0; mi < 2; mi++) {
#pragma unroll
        for (int n8 = 0; n8 < 8; n8++) {
            const int col = col_base + n8 * 8;
            const float bia0 = __ldg(&bias[col]);
            const float bia1 = __ldg(&bias[col + 1]);
#pragma unroll
            for (int half = 0; half < 2; half++) {
                const int row = row_base + mi * 16 + half * 8;
                float v0 = acc[mi][n8][half*2+0] + bia0;
                float v1 = acc[mi][n8][half*2+1] + bia1;
                float2 o;
                if (ws) { o.x = tanhf(v0); o.y = tanhf(v1); }
                else {
                    o.x = __fdividef(1.0f, 1.0f + __expf(-v0));
                    o.y = __fdividef(1.0f, 1.0f + __expf(-v1));
                }
                *reinterpret_cast<float2*>(outp + (size_t)row * DDIM + col) = o;
            }
        }
    }
}

// ---------------- scan kernel: 16384 independent recurrences over T ----------
// 32-thread blocks; 4-slot cp.async smem ring, 8 steps/chunk, 2-chunk lead.
__global__ void __launch_bounds__(32)
scan_kernel(const float* __restrict__ d_g, const float* __restrict__ b_g,
            float* __restrict__ out) {
    __shared__ __align__(16) float sA[4][8][32];
    __shared__ __align__(16) float sV[4][8][32];
    const int lane = threadIdx.x;
    const int base = blockIdx.x * 32;
    const int idx = base + lane;
    const int d = idx & (DDIM - 1);
    const float LOG2E = 1.4426950408889634f;
    const float dgl = __ldg(&d_g[d]) * LOG2E;
    const float bgl = __ldg(&b_g[d]) * LOG2E;

    float* houtp = out + (size_t)TT * SBD;   // h buffer [T+1, B, D]
    houtp[idx] = 0.0f;                       // h0

    const float* A = g_alpha;
    const float* V = g_vraw;

    const int seg = lane & 7;        // 16B segment within a 128B row
    const int r0  = lane >> 3;       // 0..3

    auto issue_chunk = [&](int c) {
        const int slot = c & 3;
#pragma unroll
        for (int rr = 0; rr < 4; rr++) {
            const int r = r0 + rr * 4;             // 0..15
            const int step = r & 7;
            const size_t gidx = (size_t)(c * 8 + step) * SBD + base + seg * 4;
            const float* src = (r < 8) ? (A + gidx) : (V + gidx);
            float* dst = (r < 8) ? &sA[slot][step][seg * 4] : &sV[slot][step][seg * 4];
            cp16(smem_u32(dst), src);
        }
        cp_commit();
    };

    issue_chunk(0);
    issue_chunk(1);
    issue_chunk(2);

    float h = 0.0f;
#pragma unroll 1
    for (int t0 = 0; t0 < TT; t0 += 8) {
        __syncwarp();
        if (t0 + 24 < TT)       { issue_chunk((t0 >> 3) + 3); cp_wait<3>(); }
        else if (t0 + 24 == TT) cp_wait<2>();
        else if (t0 + 16 == TT) cp_wait<1>();
        else                    cp_wait<0>();
        __syncwarp();

        const int slot = (t0 >> 3) & 3;
#pragma unroll
        for (int i = 0; i < 8; i++) {
            const float a  = sA[slot][i][lane];
            const float cv = sV[slot][i][lane];
            const float c  = (1.0f - a) * cv;      // off critical chain
            const float ah = a * h;                // parallel with g-chain
            const float ex = exp2f(fmaf(dgl, fabsf(h), -bgl));
            const float g = __fdividef(1.0f, 1.0f + ex);
            h = fmaf(c, g, ah);                    // h_new
            const float sg = __fdividef(1.0f, 1.0f + exp2f(-h * LOG2E));
            const size_t t = (size_t)(t0 + i);
            out[t * SBD + idx] = h * h * sg;       // h * silu(h)
            houtp[(t + 1) * SBD + idx] = h;
        }
    }
}

// ---------------- launcher ----------------
extern "C" void kernel_launch(void* const* d_in, const int* in_sizes, int n_in,
                              void* d_out, int out_size) {
    const float* x       = (const float*)d_in[0];
    const float* W_alpha = (const float*)d_in[1];
    const float* b_alpha = (const float*)d_in[2];
    const float* d_g     = (const float*)d_in[3];
    const float* b_g     = (const float*)d_in[4];
    const float* W_x     = (const float*)d_in[5];
    const float* b_v     = (const float*)d_in[6];
    float* out = (float*)d_out;

    (void)in_sizes; (void)n_in; (void)out_size;

    cudaFuncSetAttribute(gemm_kernel, cudaFuncAttributeMaxDynamicSharedMemorySize,
                         SMEM_GEMM_TOTAL);

    // 1) quantize: x -> fp16; W -> fp16 hi + raw fp16 residual
    {
        const int n4 = (int)(NELEM / 4);
        quant_x_kernel<<<(n4 + 255) / 256, 256>>>(x);
        const int w4 = 2 * DDIM * DDIM / 4;
        quant_w_kernel<<<(w4 + 255) / 256, 256>>>(W_alpha, W_x);
    }

    // 2) two fused GEMM + activation launches (alpha: sigmoid; vraw: tanh)
    {
        dim3 grid(DDIM / 256, MM / 128);
        gemm_kernel<<<grid, 512, SMEM_GEMM_TOTAL>>>(b_alpha, 0);
        gemm_kernel<<<grid, 512, SMEM_GEMM_TOTAL>>>(b_v, 1);
    }

    // 3) sequential scan, fully parallel over B*D lanes
    scan_kernel<<<SBD / 32, 32>>>(d_g, b_g, out);
}

// round 10
// speedup vs baseline: 3.5823x; 1.0283x over previous
#include <cuda_runtime.h>
#include <cuda_fp16.h>
#include <cstdint>

// ---------------- problem dims ----------------
#define TT 2048
#define BB 16
#define DDIM 1024
#define MM (TT*BB)            // 32768 rows
#define SBD (BB*DDIM)         // 16384 lanes in scan
#define NELEM ((size_t)MM*DDIM)

// ---------------- device scratch (no cudaMalloc allowed) ----------------
__device__ __half g_xh[NELEM];
__device__ __half g_wh[2*DDIM*DDIM];
__device__ float g_alpha[NELEM];
__device__ float g_vraw[NELEM];

// ---------------- PTX helpers (base sm_103 target: no tcgen05/TMA) ---------
__device__ __forceinline__ uint32_t smem_u32(const void* p) {
    uint32_t a;
    asm("{ .reg .u64 t; cvta.to.shared.u64 t, %1; cvt.u32.u64 %0, t; }" : "=r"(a) : "l"(p));
    return a;
}
__device__ __forceinline__ void cp16(uint32_t s, const void* g) {
    asm volatile("cp.async.cg.shared.global [%0], [%1], 16;" :: "r"(s), "l"(g));
}
__device__ __forceinline__ void cp_commit() {
    asm volatile("cp.async.commit_group;" ::: "memory");
}
template <int N>
__device__ __forceinline__ void cp_wait() {
    asm volatile("cp.async.wait_group %0;" :: "n"(N) : "memory");
}
__device__ __forceinline__ void ldsm4(uint32_t* r, uint32_t addr) {
    asm volatile("ldmatrix.sync.aligned.m8n8.x4.shared.b16 {%0,%1,%2,%3}, [%4];"
                 : "=r"(r[0]), "=r"(r[1]), "=r"(r[2]), "=r"(r[3]) : "r"(addr));
}
__device__ __forceinline__ void hmma(float* c, const uint32_t* a, uint32_t b0, uint32_t b1) {
    asm volatile("mma.sync.aligned.m16n8k16.row.col.f32.f16.f16.f32 "
                 "{%0,%1,%2,%3}, {%4,%5,%6,%7}, {%8,%9}, {%0,%1,%2,%3};"
                 : "+f"(c[0]), "+f"(c[1]), "+f"(c[2]), "+f"(c[3])
                 : "r"(a[0]), "r"(a[1]), "r"(a[2]), "r"(a[3]), "r"(b0), "r"(b1));
}

// ---------------- quantization kernels (fp32 -> fp16) ----------------
__global__ void quant_x_kernel(const float* __restrict__ x) {
    size_t i = (size_t)blockIdx.x * blockDim.x + threadIdx.x;  // float4 index
    if (i >= NELEM / 4) return;
    float4 v = reinterpret_cast<const float4*>(x)[i];
    float f[4] = {v.x, v.y, v.z, v.w};
    union { __half h[4]; uint2 u; } H;
#pragma unroll
    for (int j = 0; j < 4; j++) H.h[j] = __float2half_rn(f[j]);
    reinterpret_cast<uint2*>(g_xh)[i] = H.u;
}

__global__ void quant_w_kernel(const float* __restrict__ Wa, const float* __restrict__ Wx) {
    size_t i = (size_t)blockIdx.x * blockDim.x + threadIdx.x;  // float4 idx over 2 mats
    const size_t nper = (size_t)DDIM * DDIM / 4;
    if (i >= 2 * nper) return;
    const float* src = (i < nper) ? Wa : Wx;
    size_t j = (i < nper) ? i : i - nper;
    float4 v = reinterpret_cast<const float4*>(src)[j];
    float f[4] = {v.x, v.y, v.z, v.w};
    union { __half h[4]; uint2 u; } H;
#pragma unroll
    for (int k = 0; k < 4; k++) H.h[k] = __float2half_rn(f[k]);
    reinterpret_cast<uint2*>(g_wh)[i] = H.u;
}

// ---------------- GEMM: out[m,e] = act( sum_d x[m,d]*W[e,d] + bias[e] ) ------
// plain fp16, fp32 accumulate. CTA 128x256x64, 512 thr (16 warps, warp tile
// 32x64), 3-stage cp.async ring, one __syncthreads per k-chunk (16 total).
static constexpr int BK   = 64;              // k elems per chunk (128B of fp16)
static constexpr int ROWB = 144;             // 128B data + 16B pad
static constexpr int XH_TILE_B = 128 * ROWB; // 18432
static constexpr int WH_TILE_B = 256 * ROWB; // 36864
static constexpr int ST_XH = 0;
static constexpr int ST_WH = ST_XH + XH_TILE_B;
static constexpr int STAGE_B = ST_WH + WH_TILE_B;   // 55296
static constexpr int NSTAGE  = 3;
static constexpr int SMEM_GEMM_TOTAL = NSTAGE * STAGE_B;  // 165888
static constexpr int NKC = DDIM / BK;        // 16

__global__ void __launch_bounds__(512, 1)
gemm_kernel(const float* __restrict__ bias, int ws) {
    extern __shared__ char smem[];
    const uint32_t sbase = smem_u32(smem);
    const int tid = threadIdx.x;
    const int wid = tid >> 5;
    const int l   = tid & 31;
    const int wid_m = wid >> 2;      // 0..3  (32-row slabs)
    const int wid_n = wid & 3;       // 0..3  (64-col slabs)
    const int bn = blockIdx.x;       // 0..3   (N tiles of 256)
    const int bm = blockIdx.y;       // 0..255 (M tiles of 128)

    const __half* __restrict__ Xg  = g_xh + (size_t)bm * 128 * DDIM;
    const __half* __restrict__ Whg = g_wh + (size_t)ws * DDIM * DDIM + (size_t)bn * 256 * DDIM;
    float* __restrict__ outp = ws ? g_vraw : g_alpha;

    // cp.async mapping: 512 threads; 32B per thread-row-visit (2x cp16).
    // XH: 128 rows x 128B = 512 chunks of 32B (1 visit/thr);
    // WH: 256 rows x 128B = 1024 chunks (2 visits/thr).
    const int crow = tid >> 2;       // 0..127
    const int cseg = tid & 3;        // 32B segment (0..3)
    auto issue_stage = [&](int stage, int kc) {
        const uint32_t s0 = sbase + stage * STAGE_B;
        const size_t gof = (size_t)kc * BK + cseg * 16;   // halves
        const uint32_t so = cseg * 32;
        cp16(s0 + ST_XH + crow * ROWB + so,      Xg + (size_t)crow * DDIM + gof);
        cp16(s0 + ST_XH + crow * ROWB + so + 16, Xg + (size_t)crow * DDIM + gof + 8);
#pragma unroll
        for (int r2 = 0; r2 < 2; r2++) {
            const int r = crow + r2 * 128;
            cp16(s0 + ST_WH + r * ROWB + so,      Whg + (size_t)r * DDIM + gof);
            cp16(s0 + ST_WH + r * ROWB + so + 16, Whg + (size_t)r * DDIM + gof + 8);
        }
        cp_commit();
    };

    // ldmatrix lane offsets (ROWB=144: 16r mod 128 distinct -> conflict-free)
    // B map: n-slice q within an x4 load uses regs {r[2q], r[2q+1]}
    const uint32_t a_lane_off = (uint32_t)((l & 15) * ROWB + (l >> 4) * 16);
    const uint32_t b_lane_off = (uint32_t)(((l & 7) + ((l >> 4) << 3)) * ROWB + ((l >> 3) & 1) * 16);

    float acc[2][8][4];
#pragma unroll
    for (int mi = 0; mi < 2; mi++)
#pragma unroll
        for (int ni = 0; ni < 8; ni++)
#pragma unroll
            for (int r = 0; r < 4; r++) acc[mi][ni][r] = 0.0f;

    issue_stage(0, 0);
    issue_stage(1, 1);

    int rd = 0, wr = 2;
#pragma unroll 1
    for (int kc = 0; kc < NKC; kc++) {
        if (kc + 1 < NKC) cp_wait<1>(); else cp_wait<0>();
        __syncthreads();
        if (kc + 2 < NKC) issue_stage(wr, kc + 2);

        const uint32_t s0 = sbase + rd * STAGE_B;
        const uint32_t sXH = s0 + ST_XH + (uint32_t)(wid_m * 32 * ROWB) + a_lane_off;
        const uint32_t sWH = s0 + ST_WH + (uint32_t)(wid_n * 64 * ROWB) + b_lane_off;

#pragma unroll
        for (int ks = 0; ks < 4; ks++) {
            uint32_t ah[2][4];
            ldsm4(ah[0], sXH + ks * 32);
            ldsm4(ah[1], sXH + 16 * ROWB + ks * 32);
#pragma unroll
            for (int p = 0; p < 4; p++) {
                uint32_t bh[4];
                ldsm4(bh, sWH + p * 16 * ROWB + ks * 32);
#pragma unroll
                for (int mi = 0; mi < 2; mi++) {
                    hmma(acc[mi][2*p+0], ah[mi], bh[0], bh[1]);
                    hmma(acc[mi][2*p+1], ah[mi], bh[2], bh[3]);
                }
            }
        }
        rd = (rd + 1 == NSTAGE) ? 0 : rd + 1;
        wr = (wr + 1 == NSTAGE) ? 0 : wr + 1;
    }

    // epilogue: z = acc + bias; activation; float2 stores
    const int row_base = bm * 128 + wid_m * 32 + (l >> 2);
    const int col_base = bn * 256 + wid_n * 64 + (l & 3) * 2;
#pragma unroll
    for (int mi = 0; mi < 2; mi++) {
#pragma unroll
        for (int n8 = 0; n8 < 8; n8++) {
            const int col = col_base + n8 * 8;
            const float bia0 = __ldg(&bias[col]);
            const float bia1 = __ldg(&bias[col + 1]);
#pragma unroll
            for (int half = 0; half < 2; half++) {
                const int row = row_base + mi * 16 + half * 8;
                float v0 = acc[mi][n8][half*2+0] + bia0;
                float v1 = acc[mi][n8][half*2+1] + bia1;
                float2 o;
                if (ws) { o.x = tanhf(v0); o.y = tanhf(v1); }
                else {
                    o.x = __fdividef(1.0f, 1.0f + __expf(-v0));
                    o.y = __fdividef(1.0f, 1.0f + __expf(-v1));
                }
                *reinterpret_cast<float2*>(outp + (size_t)row * DDIM + col) = o;
            }
        }
    }
}

// ---------------- scan kernel: 16384 independent recurrences over T ----------
// 32-thread blocks; 4-slot cp.async smem ring, 8 steps/chunk, 2-chunk lead.
__global__ void __launch_bounds__(32)
scan_kernel(const float* __restrict__ d_g, const float* __restrict__ b_g,
            float* __restrict__ out) {
    __shared__ __align__(16) float sA[4][8][32];
    __shared__ __align__(16) float sV[4][8][32];
    const int lane = threadIdx.x;
    const int base = blockIdx.x * 32;
    const int idx = base + lane;
    const int d = idx & (DDIM - 1);
    const float LOG2E = 1.4426950408889634f;
    const float dgl = __ldg(&d_g[d]) * LOG2E;
    const float bgl = __ldg(&b_g[d]) * LOG2E;

    float* houtp = out + (size_t)TT * SBD;   // h buffer [T+1, B, D]
    houtp[idx] = 0.0f;                       // h0

    const float* A = g_alpha;
    const float* V = g_vraw;

    const int seg = lane & 7;        // 16B segment within a 128B row
    const int r0  = lane >> 3;       // 0..3

    auto issue_chunk = [&](int c) {
        const int slot = c & 3;
#pragma unroll
        for (int rr = 0; rr < 4; rr++) {
            const int r = r0 + rr * 4;             // 0..15
            const int step = r & 7;
            const size_t gidx = (size_t)(c * 8 + step) * SBD + base + seg * 4;
            const float* src = (r < 8) ? (A + gidx) : (V + gidx);
            float* dst = (r < 8) ? &sA[slot][step][seg * 4] : &sV[slot][step][seg * 4];
            cp16(smem_u32(dst), src);
        }
        cp_commit();
    };

    issue_chunk(0);
    issue_chunk(1);
    issue_chunk(2);

    float h = 0.0f;
#pragma unroll 1
    for (int t0 = 0; t0 < TT; t0 += 8) {
        __syncwarp();
        if (t0 + 24 < TT)       { issue_chunk((t0 >> 3) + 3); cp_wait<3>(); }
        else if (t0 + 24 == TT) cp_wait<2>();
        else if (t0 + 16 == TT) cp_wait<1>();
        else                    cp_wait<0>();
        __syncwarp();

        const int slot = (t0 >> 3) & 3;
#pragma unroll
        for (int i = 0; i < 8; i++) {
            const float a  = sA[slot][i][lane];
            const float cv = sV[slot][i][lane];
            const float c  = (1.0f - a) * cv;      // off critical chain
            const float ah = a * h;                // parallel with g-chain
            const float ex = exp2f(fmaf(dgl, fabsf(h), -bgl));
            const float g = __fdividef(1.0f, 1.0f + ex);
            h = fmaf(c, g, ah);                    // h_new
            const float sg = __fdividef(1.0f, 1.0f + exp2f(-h * LOG2E));
            const size_t t = (size_t)(t0 + i);
            out[t * SBD + idx] = h * h * sg;       // h * silu(h)
            houtp[(t + 1) * SBD + idx] = h;
        }
    }
}

// ---------------- launcher ----------------
extern "C" void kernel_launch(void* const* d_in, const int* in_sizes, int n_in,
                              void* d_out, int out_size) {
    const float* x       = (const float*)d_in[0];
    const float* W_alpha = (const float*)d_in[1];
    const float* b_alpha = (const float*)d_in[2];
    const float* d_g     = (const float*)d_in[3];
    const float* b_g     = (const float*)d_in[4];
    const float* W_x     = (const float*)d_in[5];
    const float* b_v     = (const float*)d_in[6];
    float* out = (float*)d_out;

    (void)in_sizes; (void)n_in; (void)out_size;

    cudaFuncSetAttribute(gemm_kernel, cudaFuncAttributeMaxDynamicSharedMemorySize,
                         SMEM_GEMM_TOTAL);

    // 1) quantize fp32 -> fp16
    {
        const int n4 = (int)(NELEM / 4);
        quant_x_kernel<<<(n4 + 255) / 256, 256>>>(x);
        const int w4 = 2 * DDIM * DDIM / 4;
        quant_w_kernel<<<(w4 + 255) / 256, 256>>>(W_alpha, W_x);
    }

    // 2) two fused GEMM + activation launches (alpha: sigmoid; vraw: tanh)
    {
        dim3 grid(DDIM / 256, MM / 128);
        gemm_kernel<<<grid, 512, SMEM_GEMM_TOTAL>>>(b_alpha, 0);
        gemm_kernel<<<grid, 512, SMEM_GEMM_TOTAL>>>(b_v, 1);
    }

    // 3) sequential scan, fully parallel over B*D lanes
    scan_kernel<<<SBD / 32, 32>>>(d_g, b_g, out);
}

// round 12
// speedup vs baseline: 4.9924x; 1.3936x over previous
#include <cuda_runtime.h>
#include <cuda_fp16.h>
#include <cstdint>

// ---------------- problem dims ----------------
#define TT 2048
#define BB 16
#define DDIM 1024
#define MM (TT*BB)            // 32768 rows
#define SBD (BB*DDIM)         // 16384 lanes in scan
#define NELEM ((size_t)MM*DDIM)

// ---------------- device scratch (no cudaMalloc allowed) ----------------
__device__ __half g_xh[NELEM];
__device__ __half g_wh[2*DDIM*DDIM];
__device__ float g_alpha[NELEM];
__device__ float g_vraw[NELEM];

// ---------------- PTX helpers (base sm_103 target: no tcgen05/TMA) ---------
__device__ __forceinline__ uint32_t smem_u32(const void* p) {
    uint32_t a;
    asm("{ .reg .u64 t; cvta.to.shared.u64 t, %1; cvt.u32.u64 %0, t; }" : "=r"(a) : "l"(p));
    return a;
}
__device__ __forceinline__ void cp16(uint32_t s, const void* g) {
    asm volatile("cp.async.cg.shared.global [%0], [%1], 16;" :: "r"(s), "l"(g));
}
__device__ __forceinline__ void cp_commit() {
    asm volatile("cp.async.commit_group;" ::: "memory");
}
template <int N>
__device__ __forceinline__ void cp_wait() {
    asm volatile("cp.async.wait_group %0;" :: "n"(N) : "memory");
}
__device__ __forceinline__ void ldsm4(uint32_t* r, uint32_t addr) {
    asm volatile("ldmatrix.sync.aligned.m8n8.x4.shared.b16 {%0,%1,%2,%3}, [%4];"
                 : "=r"(r[0]), "=r"(r[1]), "=r"(r[2]), "=r"(r[3]) : "r"(addr));
}
__device__ __forceinline__ void hmma(float* c, const uint32_t* a, uint32_t b0, uint32_t b1) {
    asm volatile("mma.sync.aligned.m16n8k16.row.col.f32.f16.f16.f32 "
                 "{%0,%1,%2,%3}, {%4,%5,%6,%7}, {%8,%9}, {%0,%1,%2,%3};"
                 : "+f"(c[0]), "+f"(c[1]), "+f"(c[2]), "+f"(c[3])
                 : "r"(a[0]), "r"(a[1]), "r"(a[2]), "r"(a[3]), "r"(b0), "r"(b1));
}

// ---------------- quantization kernels (fp32 -> fp16) ----------------
__global__ void quant_x_kernel(const float* __restrict__ x) {
    size_t i = (size_t)blockIdx.x * blockDim.x + threadIdx.x;  // float4 index
    if (i >= NELEM / 4) return;
    float4 v = reinterpret_cast<const float4*>(x)[i];
    float f[4] = {v.x, v.y, v.z, v.w};
    union { __half h[4]; uint2 u; } H;
#pragma unroll
    for (int j = 0; j < 4; j++) H.h[j] = __float2half_rn(f[j]);
    reinterpret_cast<uint2*>(g_xh)[i] = H.u;
}

__global__ void quant_w_kernel(const float* __restrict__ Wa, const float* __restrict__ Wx) {
    size_t i = (size_t)blockIdx.x * blockDim.x + threadIdx.x;  // float4 idx over 2 mats
    const size_t nper = (size_t)DDIM * DDIM / 4;
    if (i >= 2 * nper) return;
    const float* src = (i < nper) ? Wa : Wx;
    size_t j = (i < nper) ? i : i - nper;
    float4 v = reinterpret_cast<const float4*>(src)[j];
    float f[4] = {v.x, v.y, v.z, v.w};
    union { __half h[4]; uint2 u; } H;
#pragma unroll
    for (int k = 0; k < 4; k++) H.h[k] = __float2half_rn(f[k]);
    reinterpret_cast<uint2*>(g_wh)[i] = H.u;
}

// ---------------- GEMM: out[m,e] = act( sum_d x[m,d]*W[e,d] + bias[e] ) ------
// plain fp16, fp32 accumulate. CTA 128x128x64, 256 thr (8 warps, warp tile
// 32x64), 3-stage cp.async ring, TWO CTAs per SM (decoupled barrier domains).
static constexpr int BK   = 64;              // k elems per chunk (128B of fp16)
static constexpr int ROWB = 144;             // 128B data + 16B pad
static constexpr int XH_TILE_B = 128 * ROWB; // 18432
static constexpr int WH_TILE_B = 128 * ROWB; // 18432
static constexpr int ST_XH = 0;
static constexpr int ST_WH = ST_XH + XH_TILE_B;
static constexpr int STAGE_B = ST_WH + WH_TILE_B;   // 36864
static constexpr int NSTAGE  = 3;
static constexpr int SMEM_GEMM_TOTAL = NSTAGE * STAGE_B;  // 110592 (x2 CTAs = 221184)
static constexpr int NKC = DDIM / BK;        // 16

__global__ void __launch_bounds__(256, 2)
gemm_kernel(const float* __restrict__ b_alpha, const float* __restrict__ b_v) {
    extern __shared__ char smem[];
    const uint32_t sbase = smem_u32(smem);
    const int tid = threadIdx.x;
    const int wid = tid >> 5;
    const int l   = tid & 31;
    const int wid_m = wid >> 1;      // 0..3  (32-row slabs)
    const int wid_n = wid & 1;       // 0..1  (64-col slabs)
    const int bn = blockIdx.x;       // 0..7   (N tiles of 128)
    const int bm = blockIdx.y;       // 0..255 (M tiles of 128)
    const int ws = blockIdx.z;       // 0: alpha/sigmoid, 1: vraw/tanh

    const __half* __restrict__ Xg  = g_xh + (size_t)bm * 128 * DDIM;
    const __half* __restrict__ Whg = g_wh + (size_t)ws * DDIM * DDIM + (size_t)bn * 128 * DDIM;
    float* __restrict__ outp = ws ? g_vraw : g_alpha;
    const float* __restrict__ bias = ws ? b_v : b_alpha;

    // cp.async mapping: 256 threads; X,W tiles each 128 rows x 128B.
    // Each thread: one 64B half-row of X and of W (4 cp16 each).
    const int crow  = tid >> 1;      // 0..127
    const int chalf = tid & 1;       // which 64B half of the 128B k-slice
    auto issue_stage = [&](int stage, int kc) {
        const uint32_t s0 = sbase + stage * STAGE_B;
        const size_t gof = (size_t)kc * BK + chalf * 32;  // halves
        const uint32_t so = crow * ROWB + chalf * 64;
#pragma unroll
        for (int j = 0; j < 4; j++)
            cp16(s0 + ST_XH + so + j * 16, Xg + (size_t)crow * DDIM + gof + j * 8);
#pragma unroll
        for (int j = 0; j < 4; j++)
            cp16(s0 + ST_WH + so + j * 16, Whg + (size_t)crow * DDIM + gof + j * 8);
        cp_commit();
    };

    // ldmatrix lane offsets (ROWB=144: 16 rows mod 128 distinct -> conflict-free)
    // B map: n-slice q within an x4 load uses regs {r[2q], r[2q+1]}
    const uint32_t a_lane_off = (uint32_t)((l & 15) * ROWB + (l >> 4) * 16);
    const uint32_t b_lane_off = (uint32_t)(((l & 7) + ((l >> 4) << 3)) * ROWB + ((l >> 3) & 1) * 16);

    float acc[2][8][4];
#pragma unroll
    for (int mi = 0; mi < 2; mi++)
#pragma unroll
        for (int ni = 0; ni < 8; ni++)
#pragma unroll
            for (int r = 0; r < 4; r++) acc[mi][ni][r] = 0.0f;

    issue_stage(0, 0);
    issue_stage(1, 1);

    int rd = 0, wr = 2;
#pragma unroll 1
    for (int kc = 0; kc < NKC; kc++) {
        if (kc + 1 < NKC) cp_wait<1>(); else cp_wait<0>();
        __syncthreads();
        if (kc + 2 < NKC) issue_stage(wr, kc + 2);

        const uint32_t s0 = sbase + rd * STAGE_B;
        const uint32_t sXH = s0 + ST_XH + (uint32_t)(wid_m * 32 * ROWB) + a_lane_off;
        const uint32_t sWH = s0 + ST_WH + (uint32_t)(wid_n * 64 * ROWB) + b_lane_off;

#pragma unroll
        for (int ks = 0; ks < 4; ks++) {
            uint32_t ah[2][4];
            ldsm4(ah[0], sXH + ks * 32);
            ldsm4(ah[1], sXH + 16 * ROWB + ks * 32);
#pragma unroll
            for (int p = 0; p < 4; p++) {
                uint32_t bh[4];
                ldsm4(bh, sWH + p * 16 * ROWB + ks * 32);
#pragma unroll
                for (int mi = 0; mi < 2; mi++) {
                    hmma(acc[mi][2*p+0], ah[mi], bh[0], bh[1]);
                    hmma(acc[mi][2*p+1], ah[mi], bh[2], bh[3]);
                }
            }
        }
        rd = (rd + 1 == NSTAGE) ? 0 : rd + 1;
        wr = (wr + 1 == NSTAGE) ? 0 : wr + 1;
    }

    // epilogue: z = acc + bias; activation; float2 stores
    const int row_base = bm * 128 + wid_m * 32 + (l >> 2);
    const int col_base = bn * 128 + wid_n * 64 + (l & 3) * 2;
#pragma unroll
    for (int mi = 0; mi < 2; mi++) {
#pragma unroll
        for (int n8 = 0; n8 < 8; n8++) {
            const int col = col_base + n8 * 8;
            const float bia0 = __ldg(&bias[col]);
            const float bia1 = __ldg(&bias[col + 1]);
#pragma unroll
            for (int half = 0; half < 2; half++) {
                const int row = row_base + mi * 16 + half * 8;
                float v0 = acc[mi][n8][half*2+0] + bia0;
                float v1 = acc[mi][n8][half*2+1] + bia1;
                float2 o;
                if (ws) { o.x = tanhf(v0); o.y = tanhf(v1); }
                else {
                    o.x = __fdividef(1.0f, 1.0f + __expf(-v0));
                    o.y = __fdividef(1.0f, 1.0f + __expf(-v1));
                }
                *reinterpret_cast<float2*>(outp + (size_t)row * DDIM + col) = o;
            }
        }
    }
}

// ---------------- scan kernel: 16384 independent recurrences over T ----------
// 32-thread blocks; 4-slot cp.async smem ring, 8 steps/chunk, 2-chunk lead.
__global__ void __launch_bounds__(32)
scan_kernel(const float* __restrict__ d_g, const float* __restrict__ b_g,
            float* __restrict__ out) {
    __shared__ __align__(16) float sA[4][8][32];
    __shared__ __align__(16) float sV[4][8][32];
    const int lane = threadIdx.x;
    const int base = blockIdx.x * 32;
    const int idx = base + lane;
    const int d = idx & (DDIM - 1);
    const float LOG2E = 1.4426950408889634f;
    const float dgl = __ldg(&d_g[d]) * LOG2E;
    const float bgl = __ldg(&b_g[d]) * LOG2E;

    float* houtp = out + (size_t)TT * SBD;   // h buffer [T+1, B, D]
    houtp[idx] = 0.0f;                       // h0

    const float* A = g_alpha;
    const float* V = g_vraw;

    const int seg = lane & 7;        // 16B segment within a 128B row
    const int r0  = lane >> 3;       // 0..3

    auto issue_chunk = [&](int c) {
        const int slot = c & 3;
#pragma unroll
        for (int rr = 0; rr < 4; rr++) {
            const int r = r0 + rr * 4;             // 0..15
            const int step = r & 7;
            const size_t gidx = (size_t)(c * 8 + step) * SBD + base + seg * 4;
            const float* src = (r < 8) ? (A + gidx) : (V + gidx);
            float* dst = (r < 8) ? &sA[slot][step][seg * 4] : &sV[slot][step][seg * 4];
            cp16(smem_u32(dst), src);
        }
        cp_commit();
    };

    issue_chunk(0);
    issue_chunk(1);
    issue_chunk(2);

    float h = 0.0f;
#pragma unroll 1
    for (int t0 = 0; t0 < TT; t0 += 8) {
        __syncwarp();
        if (t0 + 24 < TT)       { issue_chunk((t0 >> 3) + 3); cp_wait<3>(); }
        else if (t0 + 24 == TT) cp_wait<2>();
        else if (t0 + 16 == TT) cp_wait<1>();
        else                    cp_wait<0>();
        __syncwarp();

        const int slot = (t0 >> 3) & 3;
#pragma unroll
        for (int i = 0; i < 8; i++) {
            const float a  = sA[slot][i][lane];
            const float cv = sV[slot][i][lane];
            const float c  = (1.0f - a) * cv;      // off critical chain
            const float ah = a * h;                // parallel with g-chain
            const float ex = exp2f(fmaf(dgl, fabsf(h), -bgl));
            const float g = __fdividef(1.0f, 1.0f + ex);
            h = fmaf(c, g, ah);                    // h_new
            const float sg = __fdividef(1.0f, 1.0f + exp2f(-h * LOG2E));
            const size_t t = (size_t)(t0 + i);
            out[t * SBD + idx] = h * h * sg;       // h * silu(h)
            houtp[(t + 1) * SBD + idx] = h;
        }
    }
}

// ---------------- launcher ----------------
extern "C" void kernel_launch(void* const* d_in, const int* in_sizes, int n_in,
                              void* d_out, int out_size) {
    const float* x       = (const float*)d_in[0];
    const float* W_alpha = (const float*)d_in[1];
    const float* b_alpha = (const float*)d_in[2];
    const float* d_g     = (const float*)d_in[3];
    const float* b_g     = (const float*)d_in[4];
    const float* W_x     = (const float*)d_in[5];
    const float* b_v     = (const float*)d_in[6];
    float* out = (float*)d_out;

    (void)in_sizes; (void)n_in; (void)out_size;

    cudaFuncSetAttribute(gemm_kernel, cudaFuncAttributeMaxDynamicSharedMemorySize,
                         SMEM_GEMM_TOTAL);

    // 1) quantize fp32 -> fp16
    {
        const int n4 = (int)(NELEM / 4);
        quant_x_kernel<<<(n4 + 255) / 256, 256>>>(x);
        const int w4 = 2 * DDIM * DDIM / 4;
        quant_w_kernel<<<(w4 + 255) / 256, 256>>>(W_alpha, W_x);
    }

    // 2) single fused GEMM launch (z=0: alpha/sigmoid, z=1: vraw/tanh)
    {
        dim3 grid(DDIM / 128, MM / 128, 2);
        gemm_kernel<<<grid, 256, SMEM_GEMM_TOTAL>>>(b_alpha, b_v);
    }

    // 3) sequential scan, fully parallel over B*D lanes
    scan_kernel<<<SBD / 32, 32>>>(d_g, b_g, out);
}